// round 1
// baseline (speedup 1.0000x reference)
#include <cuda_runtime.h>
#include <math.h>

// GPT-2 stack: L=8, E=1024, H=16, T=2048, B=1, DH=64, fp32.
#define TT 2048
#define EE 1024
#define NH 16
#define HD 64
#define NL 8

// ---------------- scratch (device globals; no allocation allowed) ----------
__device__ float g_h  [TT * EE];        // residual stream
__device__ float g_y  [TT * EE];        // LN output
__device__ float g_qkv[TT * 3 * EE];    // QKV
__device__ float g_att[TT * EE];        // attention output (merged heads)
__device__ float g_m1 [TT * 4 * EE];    // MLP hidden

// ---------------- LayerNorm: one block per token row ------------------------
__global__ __launch_bounds__(256) void ln_kernel(
    const float* __restrict__ h, const float* __restrict__ w,
    const float* __restrict__ b, float* __restrict__ y)
{
    const int row = blockIdx.x;
    const int tid = threadIdx.x;            // 256 threads, 4 floats each
    const float4* hr = reinterpret_cast<const float4*>(h + (size_t)row * EE);
    float4 v = hr[tid];
    float s  = v.x + v.y + v.z + v.w;
    float sq = v.x*v.x + v.y*v.y + v.z*v.z + v.w*v.w;

    // block reduce (8 warps)
    __shared__ float ss[8], ssq[8];
    #pragma unroll
    for (int off = 16; off > 0; off >>= 1) {
        s  += __shfl_xor_sync(0xffffffffu, s,  off);
        sq += __shfl_xor_sync(0xffffffffu, sq, off);
    }
    int lane = tid & 31, wid = tid >> 5;
    if (lane == 0) { ss[wid] = s; ssq[wid] = sq; }
    __syncthreads();
    if (tid == 0) {
        float S = 0.f, Q = 0.f;
        #pragma unroll
        for (int i = 0; i < 8; i++) { S += ss[i]; Q += ssq[i]; }
        ss[0] = S; ssq[0] = Q;
    }
    __syncthreads();
    const float mu  = ss[0] * (1.0f / EE);
    const float var = ssq[0] * (1.0f / EE) - mu * mu;
    const float inv = rsqrtf(var + 1e-5f);

    float4 wv = reinterpret_cast<const float4*>(w)[tid];
    float4 bv = reinterpret_cast<const float4*>(b)[tid];
    float4 o;
    o.x = (v.x - mu) * inv * wv.x + bv.x;
    o.y = (v.y - mu) * inv * wv.y + bv.y;
    o.z = (v.z - mu) * inv * wv.z + bv.z;
    o.w = (v.w - mu) * inv * wv.w + bv.w;
    reinterpret_cast<float4*>(y + (size_t)row * EE)[tid] = o;
}

// ---------------- SGEMM 128x128x16, 8x8 per thread, fused epilogues ---------
// MODE 0: C = A*B + bias
// MODE 1: C = gelu_tanh(A*B + bias)
// MODE 2: C += A*B + bias      (residual accumulate; C pre-read)
__device__ __forceinline__ float gelu_tanh(float x) {
    const float c0 = 0.7978845608028654f;   // sqrt(2/pi)
    float t = tanhf(c0 * (x + 0.044715f * x * x * x));
    return 0.5f * x * (1.0f + t);
}

template <int MODE>
__global__ __launch_bounds__(256) void sgemm_kernel(
    const float* __restrict__ A,   // [M,K] row-major
    const float* __restrict__ B,   // [K,N] row-major
    const float* __restrict__ bias,// [N]
    float* __restrict__ C,         // [M,N]
    int M, int N, int K)
{
    const int BM = 128, BN = 128, BK = 16;
    __shared__ float As[BK][BM];   // transposed A tile
    __shared__ float Bs[BK][BN];

    const int bx = blockIdx.x, by = blockIdx.y;
    const int tid = threadIdx.x;
    const int tr = tid >> 4;       // 0..15, rows
    const int tc = tid & 15;       // 0..15, cols

    const float* Ab = A + (size_t)by * BM * K;
    const float* Bb = B + (size_t)bx * BN;

    const int arow = tid >> 2;              // 0..63
    const int acol = (tid & 3) << 2;        // 0,4,8,12
    const int brow = tid >> 5;              // 0..7
    const int bcol = (tid & 31) << 2;       // 0..124

    float acc[8][8];
    #pragma unroll
    for (int i = 0; i < 8; i++)
        #pragma unroll
        for (int j = 0; j < 8; j++) acc[i][j] = 0.f;

    for (int k0 = 0; k0 < K; k0 += BK) {
        float4 a0 = *reinterpret_cast<const float4*>(Ab + (size_t)arow      * K + k0 + acol);
        float4 a1 = *reinterpret_cast<const float4*>(Ab + (size_t)(arow+64) * K + k0 + acol);
        As[acol+0][arow] = a0.x; As[acol+1][arow] = a0.y;
        As[acol+2][arow] = a0.z; As[acol+3][arow] = a0.w;
        As[acol+0][arow+64] = a1.x; As[acol+1][arow+64] = a1.y;
        As[acol+2][arow+64] = a1.z; As[acol+3][arow+64] = a1.w;

        float4 b0 = *reinterpret_cast<const float4*>(Bb + (size_t)(k0+brow)   * N + bcol);
        float4 b1 = *reinterpret_cast<const float4*>(Bb + (size_t)(k0+brow+8) * N + bcol);
        *reinterpret_cast<float4*>(&Bs[brow  ][bcol]) = b0;
        *reinterpret_cast<float4*>(&Bs[brow+8][bcol]) = b1;
        __syncthreads();

        #pragma unroll
        for (int k = 0; k < BK; k++) {
            float ra[8], rb[8];
            *reinterpret_cast<float4*>(&ra[0]) = *reinterpret_cast<const float4*>(&As[k][tr*8]);
            *reinterpret_cast<float4*>(&ra[4]) = *reinterpret_cast<const float4*>(&As[k][tr*8+4]);
            *reinterpret_cast<float4*>(&rb[0]) = *reinterpret_cast<const float4*>(&Bs[k][tc*8]);
            *reinterpret_cast<float4*>(&rb[4]) = *reinterpret_cast<const float4*>(&Bs[k][tc*8+4]);
            #pragma unroll
            for (int i = 0; i < 8; i++)
                #pragma unroll
                for (int j = 0; j < 8; j++)
                    acc[i][j] = fmaf(ra[i], rb[j], acc[i][j]);
        }
        __syncthreads();
    }

    const int crow0 = by * BM + tr * 8;
    const int ccol0 = bx * BN + tc * 8;
    float4 bv0 = *reinterpret_cast<const float4*>(bias + ccol0);
    float4 bv1 = *reinterpret_cast<const float4*>(bias + ccol0 + 4);
    const float bb[8] = {bv0.x, bv0.y, bv0.z, bv0.w, bv1.x, bv1.y, bv1.z, bv1.w};

    #pragma unroll
    for (int i = 0; i < 8; i++) {
        float* crow = C + (size_t)(crow0 + i) * N + ccol0;
        float out[8];
        #pragma unroll
        for (int j = 0; j < 8; j++) out[j] = acc[i][j] + bb[j];
        if (MODE == 1) {
            #pragma unroll
            for (int j = 0; j < 8; j++) out[j] = gelu_tanh(out[j]);
        }
        if (MODE == 2) {
            float4 c0 = *reinterpret_cast<const float4*>(crow);
            float4 c1 = *reinterpret_cast<const float4*>(crow + 4);
            out[0] += c0.x; out[1] += c0.y; out[2] += c0.z; out[3] += c0.w;
            out[4] += c1.x; out[5] += c1.y; out[6] += c1.z; out[7] += c1.w;
        }
        float4 o0 = make_float4(out[0], out[1], out[2], out[3]);
        float4 o1 = make_float4(out[4], out[5], out[6], out[7]);
        *reinterpret_cast<float4*>(crow)     = o0;
        *reinterpret_cast<float4*>(crow + 4) = o1;
    }
}

// ---------------- Flash-style causal attention ------------------------------
// grid: (T/64, H); block 256 (16x16). 64 queries, 32-key tiles, online softmax.
__global__ __launch_bounds__(256) void flash_attn_kernel(
    const float* __restrict__ qkv, float* __restrict__ att)
{
    __shared__ float Qs[64][65];
    __shared__ float Ks[32][65];
    __shared__ float Vs[32][65];
    __shared__ float Ps[64][33];

    const int qb = blockIdx.x;
    const int h  = blockIdx.y;
    const int tid = threadIdx.x;
    const int ty = tid >> 4, tx = tid & 15;
    const int q0 = qb * 64;
    const int ld = 3 * EE;
    const int qoff = h * HD;

    for (int idx = tid; idx < 64 * 64; idx += 256) {
        int r = idx >> 6, d = idx & 63;
        Qs[r][d] = qkv[(size_t)(q0 + r) * ld + qoff + d];
    }

    float O[4][4], m[4], l[4];
    #pragma unroll
    for (int i = 0; i < 4; i++) {
        m[i] = -1e30f; l[i] = 0.f;
        #pragma unroll
        for (int j = 0; j < 4; j++) O[i][j] = 0.f;
    }

    const int kbmax = (q0 + 63) >> 5;   // inclusive (causal)
    for (int kb = 0; kb <= kbmax; kb++) {
        const int k0 = kb * 32;
        for (int idx = tid; idx < 32 * 64; idx += 256) {
            int r = idx >> 6, d = idx & 63;
            Ks[r][d] = qkv[(size_t)(k0 + r) * ld +     EE + qoff + d];
            Vs[r][d] = qkv[(size_t)(k0 + r) * ld + 2 * EE + qoff + d];
        }
        __syncthreads();

        float S[4][2];
        #pragma unroll
        for (int i = 0; i < 4; i++)
            #pragma unroll
            for (int j = 0; j < 2; j++) S[i][j] = 0.f;

        #pragma unroll 8
        for (int d = 0; d < 64; d++) {
            float qv[4], kv[2];
            #pragma unroll
            for (int i = 0; i < 4; i++) qv[i] = Qs[ty*4+i][d];
            #pragma unroll
            for (int j = 0; j < 2; j++) kv[j] = Ks[tx*2+j][d];
            #pragma unroll
            for (int i = 0; i < 4; i++)
                #pragma unroll
                for (int j = 0; j < 2; j++)
                    S[i][j] = fmaf(qv[i], kv[j], S[i][j]);
        }

        // scale + causal mask (exactly like reference: masked -> -10000)
        #pragma unroll
        for (int i = 0; i < 4; i++) {
            int gq = q0 + ty*4 + i;
            #pragma unroll
            for (int j = 0; j < 2; j++) {
                int gk = k0 + tx*2 + j;
                S[i][j] = (gk <= gq) ? S[i][j] * 0.125f : -10000.0f;
            }
        }

        // online softmax (row reduce across the 16 tx lanes)
        #pragma unroll
        for (int i = 0; i < 4; i++) {
            float rm = fmaxf(S[i][0], S[i][1]);
            #pragma unroll
            for (int off = 8; off > 0; off >>= 1)
                rm = fmaxf(rm, __shfl_xor_sync(0xffffffffu, rm, off));
            float mn = fmaxf(m[i], rm);
            float p0 = __expf(S[i][0] - mn);
            float p1 = __expf(S[i][1] - mn);
            float rs = p0 + p1;
            #pragma unroll
            for (int off = 8; off > 0; off >>= 1)
                rs += __shfl_xor_sync(0xffffffffu, rs, off);
            float corr = __expf(m[i] - mn);
            l[i] = l[i] * corr + rs;
            m[i] = mn;
            #pragma unroll
            for (int j = 0; j < 4; j++) O[i][j] *= corr;
            Ps[ty*4+i][tx*2+0] = p0;
            Ps[ty*4+i][tx*2+1] = p1;
        }
        __syncthreads();

        // O += P @ V
        #pragma unroll 8
        for (int k = 0; k < 32; k++) {
            float pv[4], vv[4];
            #pragma unroll
            for (int i = 0; i < 4; i++) pv[i] = Ps[ty*4+i][k];
            #pragma unroll
            for (int j = 0; j < 4; j++) vv[j] = Vs[k][tx*4+j];
            #pragma unroll
            for (int i = 0; i < 4; i++)
                #pragma unroll
                for (int j = 0; j < 4; j++)
                    O[i][j] = fmaf(pv[i], vv[j], O[i][j]);
        }
        __syncthreads();
    }

    #pragma unroll
    for (int i = 0; i < 4; i++) {
        float invl = 1.0f / l[i];
        int gq = q0 + ty*4 + i;
        #pragma unroll
        for (int j = 0; j < 4; j++)
            att[(size_t)gq * EE + qoff + tx*4 + j] = O[i][j] * invl;
    }
}

// ---------------- host orchestration ---------------------------------------
extern "C" void kernel_launch(void* const* d_in, const int* in_sizes, int n_in,
                              void* d_out, int out_size)
{
    const float* x      = (const float*)d_in[0];
    const float* ln1_w  = (const float*)d_in[1];
    const float* ln1_b  = (const float*)d_in[2];
    const float* attn_w = (const float*)d_in[3];
    const float* attn_b = (const float*)d_in[4];
    const float* proj_w = (const float*)d_in[5];
    const float* proj_b = (const float*)d_in[6];
    const float* ln2_w  = (const float*)d_in[7];
    const float* ln2_b  = (const float*)d_in[8];
    const float* fc_w   = (const float*)d_in[9];
    const float* fc_b   = (const float*)d_in[10];
    const float* fc2_w  = (const float*)d_in[11];
    const float* fc2_b  = (const float*)d_in[12];

    float *h, *y, *qkv, *att, *m1;
    cudaGetSymbolAddress((void**)&h,   g_h);
    cudaGetSymbolAddress((void**)&y,   g_y);
    cudaGetSymbolAddress((void**)&qkv, g_qkv);
    cudaGetSymbolAddress((void**)&att, g_att);
    cudaGetSymbolAddress((void**)&m1,  g_m1);

    cudaMemcpyAsync(h, x, (size_t)TT * EE * sizeof(float),
                    cudaMemcpyDeviceToDevice, 0);

    const dim3 blk(256);
    const dim3 gLN(TT);
    const dim3 gQKV(3 * EE / 128, TT / 128);   // (24,16)
    const dim3 gPROJ(EE / 128, TT / 128);      // (8,16)
    const dim3 gFC(4 * EE / 128, TT / 128);    // (32,16)
    const dim3 gFC2(EE / 128, TT / 128);       // (8,16)
    const dim3 gATT(TT / 64, NH);              // (32,16)

    for (int lyr = 0; lyr < NL; lyr++) {
        const float* aw  = attn_w + (size_t)lyr * EE * 3 * EE;
        const float* ab  = attn_b + (size_t)lyr * 3 * EE;
        const float* pw  = proj_w + (size_t)lyr * EE * EE;
        const float* pb  = proj_b + (size_t)lyr * EE;
        const float* fw  = fc_w   + (size_t)lyr * EE * 4 * EE;
        const float* fb  = fc_b   + (size_t)lyr * 4 * EE;
        const float* f2w = fc2_w  + (size_t)lyr * 4 * EE * EE;
        const float* f2b = fc2_b  + (size_t)lyr * EE;

        // attn block
        ln_kernel<<<gLN, blk>>>(h, ln1_w + (size_t)lyr * EE, ln1_b + (size_t)lyr * EE, y);
        sgemm_kernel<0><<<gQKV, blk>>>(y, aw, ab, qkv, TT, 3 * EE, EE);
        flash_attn_kernel<<<gATT, blk>>>(qkv, att);
        sgemm_kernel<2><<<gPROJ, blk>>>(att, pw, pb, h, TT, EE, EE);

        // MLP block
        ln_kernel<<<gLN, blk>>>(h, ln2_w + (size_t)lyr * EE, ln2_b + (size_t)lyr * EE, y);
        sgemm_kernel<1><<<gFC, blk>>>(y, fw, fb, m1, TT, 4 * EE, EE);
        sgemm_kernel<2><<<gFC2, blk>>>(m1, f2w, f2b, h, TT, EE, 4 * EE);
    }

    cudaMemcpyAsync(d_out, h, (size_t)TT * EE * sizeof(float),
                    cudaMemcpyDeviceToDevice, 0);
}

// round 2
// speedup vs baseline: 1.9130x; 1.9130x over previous
#include <cuda_runtime.h>
#include <math.h>
#include <stdint.h>

// GPT-2 stack: L=8, E=1024, H=16, T=2048, B=1, DH=64, fp32 in/out.
#define TT 2048
#define EE 1024
#define NH 16
#define HD 64
#define NL 8

// ---------------- scratch (device globals; no allocation allowed) ----------
__device__ float g_h  [TT * EE];        // residual stream
__device__ float g_y  [TT * EE];        // LN output
__device__ float g_qkv[TT * 3 * EE];    // QKV
__device__ float g_att[TT * EE];        // attention output (merged heads)
__device__ float g_m1 [TT * 4 * EE];    // MLP hidden

// ---------------- LayerNorm: one block per token row ------------------------
__global__ __launch_bounds__(256) void ln_kernel(
    const float* __restrict__ h, const float* __restrict__ w,
    const float* __restrict__ b, float* __restrict__ y)
{
    const int row = blockIdx.x;
    const int tid = threadIdx.x;            // 256 threads, 4 floats each
    const float4* hr = reinterpret_cast<const float4*>(h + (size_t)row * EE);
    float4 v = hr[tid];
    float s  = v.x + v.y + v.z + v.w;
    float sq = v.x*v.x + v.y*v.y + v.z*v.z + v.w*v.w;

    __shared__ float ss[8], ssq[8];
    #pragma unroll
    for (int off = 16; off > 0; off >>= 1) {
        s  += __shfl_xor_sync(0xffffffffu, s,  off);
        sq += __shfl_xor_sync(0xffffffffu, sq, off);
    }
    int lane = tid & 31, wid = tid >> 5;
    if (lane == 0) { ss[wid] = s; ssq[wid] = sq; }
    __syncthreads();
    if (tid == 0) {
        float S = 0.f, Q = 0.f;
        #pragma unroll
        for (int i = 0; i < 8; i++) { S += ss[i]; Q += ssq[i]; }
        ss[0] = S; ssq[0] = Q;
    }
    __syncthreads();
    const float mu  = ss[0] * (1.0f / EE);
    const float var = ssq[0] * (1.0f / EE) - mu * mu;
    const float inv = rsqrtf(var + 1e-5f);

    float4 wv = reinterpret_cast<const float4*>(w)[tid];
    float4 bv = reinterpret_cast<const float4*>(b)[tid];
    float4 o;
    o.x = (v.x - mu) * inv * wv.x + bv.x;
    o.y = (v.y - mu) * inv * wv.y + bv.y;
    o.z = (v.z - mu) * inv * wv.z + bv.z;
    o.w = (v.w - mu) * inv * wv.w + bv.w;
    reinterpret_cast<float4*>(y + (size_t)row * EE)[tid] = o;
}

// ---------------- TF32 tensor-core GEMM -------------------------------------
// C[M,N] = epilogue(A[M,K] @ B[K,N] + bias)
// MODE 0: bias only; MODE 1: gelu(x+bias); MODE 2: C += x + bias (residual)
// Tile 128x128x32, 256 threads (8 warps), warp tile 32x64, mma m16n8k8 tf32.

__device__ __forceinline__ float gelu_tanh(float x) {
    const float c0 = 0.7978845608028654f;   // sqrt(2/pi)
    float t = tanhf(c0 * (x + 0.044715f * x * x * x));
    return 0.5f * x * (1.0f + t);
}

__device__ __forceinline__ uint32_t f2tf32(float x) {
    uint32_t r;
    asm("cvt.rna.tf32.f32 %0, %1;" : "=r"(r) : "f"(x));
    return r;
}

__device__ __forceinline__ void mma_tf32(float c[4], const uint32_t a[4], const uint32_t b[2]) {
    asm volatile(
        "mma.sync.aligned.m16n8k8.row.col.f32.tf32.tf32.f32 "
        "{%0,%1,%2,%3}, {%4,%5,%6,%7}, {%8,%9}, {%0,%1,%2,%3};\n"
        : "+f"(c[0]), "+f"(c[1]), "+f"(c[2]), "+f"(c[3])
        : "r"(a[0]), "r"(a[1]), "r"(a[2]), "r"(a[3]),
          "r"(b[0]), "r"(b[1]));
}

#define CP16(dst, src) asm volatile("cp.async.cg.shared.global [%0], [%1], 16;\n" :: "r"(dst), "l"(src))
#define CP_COMMIT()    asm volatile("cp.async.commit_group;\n")
#define CP_WAIT(n)     asm volatile("cp.async.wait_group %0;\n" :: "n"(n))

// smem strides (floats): chosen for conflict-free fragment loads
#define AST 36    // As[m][k]: (36m+k)%32 = (4m+k)%32 -> bijective over warp
#define BST 136   // Bs[k][n]: (136k+n)%32 = (8k+n)%32 -> bijective over warp
#define A_SZ (128 * AST)
#define B_SZ (32 * BST)
#define GEMM_SMEM ((A_SZ + B_SZ) * 2 * 4)

template <int MODE>
__global__ __launch_bounds__(256, 2) void mma_gemm(
    const float* __restrict__ A, const float* __restrict__ B,
    const float* __restrict__ bias, float* __restrict__ C,
    int M, int N, int K)
{
    extern __shared__ float sm[];
    float* Abuf[2] = { sm,               sm + A_SZ + B_SZ };
    float* Bbuf[2] = { sm + A_SZ,        sm + 2*A_SZ + B_SZ };

    const int tid  = threadIdx.x;
    const int lane = tid & 31;
    const int warp = tid >> 5;
    const int wm   = (warp & 3) * 32;    // warp m offset (4 warps over 128)
    const int wn   = (warp >> 2) * 64;   // warp n offset (2 warps over 128)
    const int g    = lane >> 2;          // group id 0..7
    const int tk   = lane & 3;           // thread-in-group 0..3

    const int bm = blockIdx.y * 128;
    const int bn = blockIdx.x * 128;

    uint32_t a_s[2], b_s[2];
    a_s[0] = (uint32_t)__cvta_generic_to_shared(Abuf[0]);
    a_s[1] = (uint32_t)__cvta_generic_to_shared(Abuf[1]);
    b_s[0] = (uint32_t)__cvta_generic_to_shared(Bbuf[0]);
    b_s[1] = (uint32_t)__cvta_generic_to_shared(Bbuf[1]);

    float acc[2][8][4];
    #pragma unroll
    for (int mt = 0; mt < 2; mt++)
        #pragma unroll
        for (int nt = 0; nt < 8; nt++)
            #pragma unroll
            for (int i = 0; i < 4; i++) acc[mt][nt][i] = 0.f;

    auto load_tile = [&](int buf, int k0) {
        #pragma unroll
        for (int i = 0; i < 4; i++) {
            int idx = tid + 256 * i;
            int r = idx >> 3, c = (idx & 7) * 4;      // 128 rows x 8 chunks
            CP16(a_s[buf] + (uint32_t)(r * AST + c) * 4,
                 A + (size_t)(bm + r) * K + k0 + c);
        }
        #pragma unroll
        for (int i = 0; i < 4; i++) {
            int idx = tid + 256 * i;
            int r = idx >> 5, c = (idx & 31) * 4;     // 32 rows x 32 chunks
            CP16(b_s[buf] + (uint32_t)(r * BST + c) * 4,
                 B + (size_t)(k0 + r) * N + bn + c);
        }
        CP_COMMIT();
    };

    const int nk = K / 32;
    load_tile(0, 0);

    for (int t = 0; t < nk; t++) {
        const int buf = t & 1;
        if (t + 1 < nk) {
            load_tile(buf ^ 1, (t + 1) * 32);
            CP_WAIT(1);
        } else {
            CP_WAIT(0);
        }
        __syncthreads();

        const float* Ab = Abuf[buf];
        const float* Bb = Bbuf[buf];

        #pragma unroll
        for (int kk = 0; kk < 4; kk++) {
            uint32_t af[2][4], bf[8][2];
            const int kc = kk * 8;
            #pragma unroll
            for (int mt = 0; mt < 2; mt++) {
                int r0 = wm + mt * 16;
                af[mt][0] = f2tf32(Ab[(r0 + g    ) * AST + kc + tk    ]);
                af[mt][1] = f2tf32(Ab[(r0 + g + 8) * AST + kc + tk    ]);
                af[mt][2] = f2tf32(Ab[(r0 + g    ) * AST + kc + tk + 4]);
                af[mt][3] = f2tf32(Ab[(r0 + g + 8) * AST + kc + tk + 4]);
            }
            #pragma unroll
            for (int nt = 0; nt < 8; nt++) {
                int c0 = wn + nt * 8 + g;
                bf[nt][0] = f2tf32(Bb[(kc + tk    ) * BST + c0]);
                bf[nt][1] = f2tf32(Bb[(kc + tk + 4) * BST + c0]);
            }
            #pragma unroll
            for (int mt = 0; mt < 2; mt++)
                #pragma unroll
                for (int nt = 0; nt < 8; nt++)
                    mma_tf32(acc[mt][nt], af[mt], bf[nt]);
        }
        __syncthreads();
    }

    // epilogue: thread owns rows (g, g+8) of each 16x8 tile, cols 2tk,2tk+1
    #pragma unroll
    for (int mt = 0; mt < 2; mt++) {
        const int row0 = bm + wm + mt * 16 + g;
        #pragma unroll
        for (int nt = 0; nt < 8; nt++) {
            const int col = bn + wn + nt * 8 + 2 * tk;
            float2 bv = *reinterpret_cast<const float2*>(bias + col);
            float o0 = acc[mt][nt][0] + bv.x;
            float o1 = acc[mt][nt][1] + bv.y;
            float o2 = acc[mt][nt][2] + bv.x;
            float o3 = acc[mt][nt][3] + bv.y;
            if (MODE == 1) {
                o0 = gelu_tanh(o0); o1 = gelu_tanh(o1);
                o2 = gelu_tanh(o2); o3 = gelu_tanh(o3);
            }
            float* p0 = C + (size_t)row0 * N + col;
            float* p1 = C + (size_t)(row0 + 8) * N + col;
            if (MODE == 2) {
                float2 c0 = *reinterpret_cast<const float2*>(p0);
                float2 c1 = *reinterpret_cast<const float2*>(p1);
                o0 += c0.x; o1 += c0.y; o2 += c1.x; o3 += c1.y;
            }
            *reinterpret_cast<float2*>(p0) = make_float2(o0, o1);
            *reinterpret_cast<float2*>(p1) = make_float2(o2, o3);
        }
    }
}

// ---------------- Flash-style causal attention ------------------------------
__global__ __launch_bounds__(256) void flash_attn_kernel(
    const float* __restrict__ qkv, float* __restrict__ att)
{
    __shared__ float Qs[64][65];
    __shared__ float Ks[32][65];
    __shared__ float Vs[32][65];
    __shared__ float Ps[64][33];

    const int qb = blockIdx.x;
    const int h  = blockIdx.y;
    const int tid = threadIdx.x;
    const int ty = tid >> 4, tx = tid & 15;
    const int q0 = qb * 64;
    const int ld = 3 * EE;
    const int qoff = h * HD;

    for (int idx = tid; idx < 64 * 64; idx += 256) {
        int r = idx >> 6, d = idx & 63;
        Qs[r][d] = qkv[(size_t)(q0 + r) * ld + qoff + d];
    }

    float O[4][4], m[4], l[4];
    #pragma unroll
    for (int i = 0; i < 4; i++) {
        m[i] = -1e30f; l[i] = 0.f;
        #pragma unroll
        for (int j = 0; j < 4; j++) O[i][j] = 0.f;
    }

    const int kbmax = (q0 + 63) >> 5;   // inclusive (causal)
    for (int kb = 0; kb <= kbmax; kb++) {
        const int k0 = kb * 32;
        for (int idx = tid; idx < 32 * 64; idx += 256) {
            int r = idx >> 6, d = idx & 63;
            Ks[r][d] = qkv[(size_t)(k0 + r) * ld +     EE + qoff + d];
            Vs[r][d] = qkv[(size_t)(k0 + r) * ld + 2 * EE + qoff + d];
        }
        __syncthreads();

        float S[4][2];
        #pragma unroll
        for (int i = 0; i < 4; i++)
            #pragma unroll
            for (int j = 0; j < 2; j++) S[i][j] = 0.f;

        #pragma unroll 8
        for (int d = 0; d < 64; d++) {
            float qv[4], kv[2];
            #pragma unroll
            for (int i = 0; i < 4; i++) qv[i] = Qs[ty*4+i][d];
            #pragma unroll
            for (int j = 0; j < 2; j++) kv[j] = Ks[tx*2+j][d];
            #pragma unroll
            for (int i = 0; i < 4; i++)
                #pragma unroll
                for (int j = 0; j < 2; j++)
                    S[i][j] = fmaf(qv[i], kv[j], S[i][j]);
        }

        #pragma unroll
        for (int i = 0; i < 4; i++) {
            int gq = q0 + ty*4 + i;
            #pragma unroll
            for (int j = 0; j < 2; j++) {
                int gk = k0 + tx*2 + j;
                S[i][j] = (gk <= gq) ? S[i][j] * 0.125f : -10000.0f;
            }
        }

        #pragma unroll
        for (int i = 0; i < 4; i++) {
            float rm = fmaxf(S[i][0], S[i][1]);
            #pragma unroll
            for (int off = 8; off > 0; off >>= 1)
                rm = fmaxf(rm, __shfl_xor_sync(0xffffffffu, rm, off));
            float mn = fmaxf(m[i], rm);
            float p0 = __expf(S[i][0] - mn);
            float p1 = __expf(S[i][1] - mn);
            float rs = p0 + p1;
            #pragma unroll
            for (int off = 8; off > 0; off >>= 1)
                rs += __shfl_xor_sync(0xffffffffu, rs, off);
            float corr = __expf(m[i] - mn);
            l[i] = l[i] * corr + rs;
            m[i] = mn;
            #pragma unroll
            for (int j = 0; j < 4; j++) O[i][j] *= corr;
            Ps[ty*4+i][tx*2+0] = p0;
            Ps[ty*4+i][tx*2+1] = p1;
        }
        __syncthreads();

        #pragma unroll 8
        for (int k = 0; k < 32; k++) {
            float pv[4], vv[4];
            #pragma unroll
            for (int i = 0; i < 4; i++) pv[i] = Ps[ty*4+i][k];
            #pragma unroll
            for (int j = 0; j < 4; j++) vv[j] = Vs[k][tx*4+j];
            #pragma unroll
            for (int i = 0; i < 4; i++)
                #pragma unroll
                for (int j = 0; j < 4; j++)
                    O[i][j] = fmaf(pv[i], vv[j], O[i][j]);
        }
        __syncthreads();
    }

    #pragma unroll
    for (int i = 0; i < 4; i++) {
        float invl = 1.0f / l[i];
        int gq = q0 + ty*4 + i;
        #pragma unroll
        for (int j = 0; j < 4; j++)
            att[(size_t)gq * EE + qoff + tx*4 + j] = O[i][j] * invl;
    }
}

// ---------------- host orchestration ---------------------------------------
extern "C" void kernel_launch(void* const* d_in, const int* in_sizes, int n_in,
                              void* d_out, int out_size)
{
    const float* x      = (const float*)d_in[0];
    const float* ln1_w  = (const float*)d_in[1];
    const float* ln1_b  = (const float*)d_in[2];
    const float* attn_w = (const float*)d_in[3];
    const float* attn_b = (const float*)d_in[4];
    const float* proj_w = (const float*)d_in[5];
    const float* proj_b = (const float*)d_in[6];
    const float* ln2_w  = (const float*)d_in[7];
    const float* ln2_b  = (const float*)d_in[8];
    const float* fc_w   = (const float*)d_in[9];
    const float* fc_b   = (const float*)d_in[10];
    const float* fc2_w  = (const float*)d_in[11];
    const float* fc2_b  = (const float*)d_in[12];

    float *h, *y, *qkv, *att, *m1;
    cudaGetSymbolAddress((void**)&h,   g_h);
    cudaGetSymbolAddress((void**)&y,   g_y);
    cudaGetSymbolAddress((void**)&qkv, g_qkv);
    cudaGetSymbolAddress((void**)&att, g_att);
    cudaGetSymbolAddress((void**)&m1,  g_m1);

    cudaFuncSetAttribute(mma_gemm<0>, cudaFuncAttributeMaxDynamicSharedMemorySize, GEMM_SMEM);
    cudaFuncSetAttribute(mma_gemm<1>, cudaFuncAttributeMaxDynamicSharedMemorySize, GEMM_SMEM);
    cudaFuncSetAttribute(mma_gemm<2>, cudaFuncAttributeMaxDynamicSharedMemorySize, GEMM_SMEM);

    cudaMemcpyAsync(h, x, (size_t)TT * EE * sizeof(float),
                    cudaMemcpyDeviceToDevice, 0);

    const dim3 blk(256);
    const dim3 gLN(TT);
    const dim3 gQKV(3 * EE / 128, TT / 128);   // (24,16)
    const dim3 gPROJ(EE / 128, TT / 128);      // (8,16)
    const dim3 gFC(4 * EE / 128, TT / 128);    // (32,16)
    const dim3 gFC2(EE / 128, TT / 128);       // (8,16)
    const dim3 gATT(TT / 64, NH);              // (32,16)

    for (int lyr = 0; lyr < NL; lyr++) {
        const float* aw  = attn_w + (size_t)lyr * EE * 3 * EE;
        const float* ab  = attn_b + (size_t)lyr * 3 * EE;
        const float* pw  = proj_w + (size_t)lyr * EE * EE;
        const float* pb  = proj_b + (size_t)lyr * EE;
        const float* fw  = fc_w   + (size_t)lyr * EE * 4 * EE;
        const float* fb  = fc_b   + (size_t)lyr * 4 * EE;
        const float* f2w = fc2_w  + (size_t)lyr * 4 * EE * EE;
        const float* f2b = fc2_b  + (size_t)lyr * EE;

        // attn block
        ln_kernel<<<gLN, blk>>>(h, ln1_w + (size_t)lyr * EE, ln1_b + (size_t)lyr * EE, y);
        mma_gemm<0><<<gQKV, blk, GEMM_SMEM>>>(y, aw, ab, qkv, TT, 3 * EE, EE);
        flash_attn_kernel<<<gATT, blk>>>(qkv, att);
        mma_gemm<2><<<gPROJ, blk, GEMM_SMEM>>>(att, pw, pb, h, TT, EE, EE);

        // MLP block
        ln_kernel<<<gLN, blk>>>(h, ln2_w + (size_t)lyr * EE, ln2_b + (size_t)lyr * EE, y);
        mma_gemm<1><<<gFC, blk, GEMM_SMEM>>>(y, fw, fb, m1, TT, 4 * EE, EE);
        mma_gemm<2><<<gFC2, blk, GEMM_SMEM>>>(m1, f2w, f2b, h, TT, EE, 4 * EE);
    }

    cudaMemcpyAsync(d_out, h, (size_t)TT * EE * sizeof(float),
                    cudaMemcpyDeviceToDevice, 0);
}